// round 6
// baseline (speedup 1.0000x reference)
#include <cuda_runtime.h>
#include <cuda_bf16.h>
#include <math.h>
#include <stdint.h>

// Problem constants
#define BATCH 2
#define SEQ   2048
#define NH    32
#define HD    128
#define HID   4096           // NH*HD
#define QKVN  12288          // 3*HID
#define MTOK  (BATCH*SEQ)    // 4096 tokens

// GEMM tile config (mma.sync m16n8k8 tf32, ldmatrix fragments)
#define BM 128
#define BN 128
#define BK 32
#define STAGES 3
#define TSTRIDE 36                               // floats per smem row (144 B)
#define TILE_BYTES (128 * TSTRIDE * 4)           // 18432 (A and B identical)
#define STAGE_BYTES (2 * TILE_BYTES)             // 36864
#define GEMM_SMEM (STAGES * STAGE_BYTES)         // 110592

// ---------------- scratch (device globals) -------------
__device__ float g_qkv[(size_t)MTOK * QKVN];
__device__ float g_q[(size_t)MTOK * HID];
__device__ float g_k[(size_t)MTOK * HID];
__device__ float g_ctx[(size_t)MTOK * HID];          // tf32-rounded at attn store
__device__ float g_hidr[(size_t)MTOK * HID];         // tf32-rounded hidden
// transposed + tf32-rounded weights, each [N][HID]
#define WR_VQ 0
#define WR_LQ ((size_t)HID * QKVN)
#define WR_VD (2 * (size_t)HID * QKVN)
#define WR_LD (2 * (size_t)HID * QKVN + (size_t)HID * HID)
__device__ float g_wr[2 * (size_t)HID * QKVN + 2 * (size_t)HID * HID];
__device__ int   g_cnt[2];
__device__ int   g_idx[2][MTOK];

// ---------------- helpers ----------------
__device__ __forceinline__ uint32_t smem_u32(const void* p) {
    uint32_t a;
    asm("{ .reg .u64 t; cvta.to.shared.u64 t, %1; cvt.u32.u64 %0, t; }" : "=r"(a) : "l"(p));
    return a;
}
__device__ __forceinline__ void cp16(uint32_t dst, const void* src) {
    asm volatile("cp.async.cg.shared.global [%0], [%1], 16;" :: "r"(dst), "l"(src));
}
__device__ __forceinline__ void cp_commit() {
    asm volatile("cp.async.commit_group;" ::: "memory");
}
template <int N>
__device__ __forceinline__ void cp_wait() {
    asm volatile("cp.async.wait_group %0;" :: "n"(N) : "memory");
}
__device__ __forceinline__ uint32_t f2tf32(float f) {
    uint32_t r;
    asm("cvt.rna.tf32.f32 %0, %1;" : "=r"(r) : "f"(f));
    return r;
}
__device__ __forceinline__ float tf32r(float f) { return __uint_as_float(f2tf32(f)); }
__device__ __forceinline__ void mma_tf32(float* c, uint32_t a0, uint32_t a1, uint32_t a2, uint32_t a3,
                                         uint32_t b0, uint32_t b1) {
    asm volatile(
        "mma.sync.aligned.m16n8k8.row.col.f32.tf32.tf32.f32 "
        "{%0,%1,%2,%3}, {%4,%5,%6,%7}, {%8,%9}, {%0,%1,%2,%3};"
        : "+f"(c[0]), "+f"(c[1]), "+f"(c[2]), "+f"(c[3])
        : "r"(a0), "r"(a1), "r"(a2), "r"(a3), "r"(b0), "r"(b1));
}
#define LDSM4(r0, r1, r2, r3, addr)                                               \
    asm volatile("ldmatrix.sync.aligned.m8n8.x4.shared.b16 {%0,%1,%2,%3}, [%4];"   \
        : "=r"(r0), "=r"(r1), "=r"(r2), "=r"(r3) : "r"(addr))

// ---------------- pre-passes ----------------
// round hidden to tf32 (A side)
__global__ __launch_bounds__(256)
void round_tf32_kernel(const float4* __restrict__ in, float4* __restrict__ out, int n4) {
    int i = blockIdx.x * blockDim.x + threadIdx.x;
    if (i >= n4) return;
    float4 v = in[i];
    out[i] = make_float4(tf32r(v.x), tf32r(v.y), tf32r(v.z), tf32r(v.w));
}
// transpose + round weights: W[K=HID][N] -> Wt[N][HID]
__global__ __launch_bounds__(256)
void trp_round_kernel(const float* __restrict__ W, float* __restrict__ Wt, int N) {
    __shared__ float t[32][33];
    int bx = blockIdx.x * 32;   // n
    int by = blockIdx.y * 32;   // k
    int x = threadIdx.x & 31;
    int y = threadIdx.x >> 5;   // 0..7
#pragma unroll
    for (int i = 0; i < 32; i += 8)
        t[y + i][x] = W[(size_t)(by + y + i) * N + bx + x];
    __syncthreads();
#pragma unroll
    for (int i = 0; i < 32; i += 8)
        Wt[(size_t)(bx + y + i) * HID + by + x] = tf32r(t[x][y + i]);
}

// ---------------- mask / routing ----------------
__global__ void zero_cnt_kernel() {
    if (threadIdx.x < 2) g_cnt[threadIdx.x] = 0;
}
__global__ void route_kernel(const int* __restrict__ tt) {
    int idx = blockIdx.x * blockDim.x + threadIdx.x;
    if (idx >= MTOK) return;
    int s = idx & (SEQ - 1);
    int vis = (s + 1 < SEQ) && (tt[idx] == 1) && (tt[idx + 1] == 1);
    int e = vis ? 0 : 1;
    int pos = atomicAdd(&g_cnt[e], 1);
    g_idx[e][pos] = idx;
}

// ---------------- tensor-core tf32 GEMM (ldmatrix fragments) ----------------
// C[m][n] = sum_k A[m][k] * Wt[n][k] over gathered expert rows.
// A smem: [128 m][BK k], row stride 36 floats. B smem: [128 n][BK k], same.
__global__ __launch_bounds__(256)
void gemm_tc(const float* __restrict__ A, const float* __restrict__ Wt,
             float* __restrict__ C, int N,
             const int* __restrict__ idx, const int* __restrict__ cnt_ptr) {
    __shared__ int idx_s[BM];
    extern __shared__ char smem[];
    const uint32_t sb = smem_u32(smem);
    const int tid = threadIdx.x;
    const int wid = tid >> 5;
    const int lane = tid & 31;
    const int lm = lane >> 2;
    const int lq = lane & 3;
    const int warp_m = wid & 1;
    const int warp_n = wid >> 1;
    const int m0 = blockIdx.x * BM;
    const int n0 = blockIdx.y * BN;

    const int count = __ldg(cnt_ptr);
    if (m0 >= count) return;

    if (tid < BM) {
        int mp = m0 + tid;
        idx_s[tid] = idx[mp < count ? mp : count - 1];
    }
    __syncthreads();

    // loader indices: 128 rows x 8 16B-granules for each of A and B
    int r_ld[4], c_ld[4];
#pragma unroll
    for (int i = 0; i < 4; i++) {
        int t = tid + i * 256;
        r_ld[i] = t >> 3;
        c_ld[i] = t & 7;
    }
    int a_g[4];
#pragma unroll
    for (int i = 0; i < 4; i++) a_g[i] = idx_s[r_ld[i]];

    const float* Bt = Wt + (size_t)n0 * HID;

    auto load_stage = [&](int stage, int chunk) {
        uint32_t as = sb + stage * STAGE_BYTES;
        uint32_t bs = as + TILE_BYTES;
#pragma unroll
        for (int i = 0; i < 4; i++)
            cp16(as + r_ld[i] * (TSTRIDE * 4) + c_ld[i] * 16,
                 A + (size_t)a_g[i] * HID + chunk * BK + c_ld[i] * 4);
#pragma unroll
        for (int i = 0; i < 4; i++)
            cp16(bs + r_ld[i] * (TSTRIDE * 4) + c_ld[i] * 16,
                 Bt + (size_t)r_ld[i] * HID + chunk * BK + c_ld[i] * 4);
    };

    // per-lane ldmatrix address components
    const int a_row = (lane & 7) | (lane & 8);           // 0..15
    const int a_ko  = (lane >> 4) * 4;                   // 0 or 4
    const int b_row = (lane & 7) | ((lane >> 1) & 8);    // lane>=16 -> +8
    const int b_ko  = ((lane >> 3) & 1) * 4;             // 0 or 4
    const uint32_t a_off = (warp_m * 64 + a_row) * (TSTRIDE * 4) + a_ko * 4;
    const uint32_t b_off = (warp_n * 32 + b_row) * (TSTRIDE * 4) + b_ko * 4;

    float c[4][4][4];
#pragma unroll
    for (int mt = 0; mt < 4; mt++)
#pragma unroll
        for (int nt = 0; nt < 4; nt++)
#pragma unroll
            for (int j = 0; j < 4; j++) c[mt][nt][j] = 0.f;

    const int NC = HID / BK;

    load_stage(0, 0); cp_commit();
    load_stage(1, 1); cp_commit();

    for (int ch = 0; ch < NC; ch++) {
        cp_wait<1>();
        __syncthreads();

        if (ch + 2 < NC) load_stage((ch + 2) % STAGES, ch + 2);
        cp_commit();

        const uint32_t as = sb + (ch % STAGES) * STAGE_BYTES;
        const uint32_t bs = as + TILE_BYTES;
        const uint32_t aL = as + a_off;
        const uint32_t bL = bs + b_off;

#pragma unroll
        for (int kk = 0; kk < BK; kk += 8) {
            uint32_t af[4][4], bf[4][2];
#pragma unroll
            for (int mt = 0; mt < 4; mt++)
                LDSM4(af[mt][0], af[mt][1], af[mt][2], af[mt][3],
                      aL + mt * 16 * (TSTRIDE * 4) + kk * 4);
#pragma unroll
            for (int pr = 0; pr < 2; pr++)
                LDSM4(bf[2 * pr][0], bf[2 * pr][1], bf[2 * pr + 1][0], bf[2 * pr + 1][1],
                      bL + pr * 16 * (TSTRIDE * 4) + kk * 4);
#pragma unroll
            for (int mt = 0; mt < 4; mt++)
#pragma unroll
                for (int nt = 0; nt < 4; nt++)
                    mma_tf32(c[mt][nt], af[mt][0], af[mt][1], af[mt][2], af[mt][3],
                             bf[nt][0], bf[nt][1]);
        }
        __syncthreads();
    }

    // epilogue: scatter to true rows; skip padding rows
#pragma unroll
    for (int mt = 0; mt < 4; mt++) {
        int r0 = warp_m * 64 + mt * 16 + lm;
        int r1 = r0 + 8;
        bool on0 = (m0 + r0 < count);
        bool on1 = (m0 + r1 < count);
        float* p0 = C + (size_t)idx_s[r0] * N + n0 + warp_n * 32;
        float* p1 = C + (size_t)idx_s[r1] * N + n0 + warp_n * 32;
#pragma unroll
        for (int nt = 0; nt < 4; nt++) {
            int col = nt * 8 + 2 * lq;
            if (on0) *(float2*)(p0 + col) = make_float2(c[mt][nt][0], c[mt][nt][1]);
            if (on1) *(float2*)(p1 + col) = make_float2(c[mt][nt][2], c[mt][nt][3]);
        }
    }
}

// ---------------- RoPE ----------------
__global__ void rope_kernel(const float* __restrict__ qkv, const int* __restrict__ pos_ids,
                            float* __restrict__ q, float* __restrict__ k) {
    int idx = blockIdx.x * blockDim.x + threadIdx.x;
    if (idx >= MTOK * NH * 64) return;
    int i = idx & 63;
    int h = (idx >> 6) & 31;
    int m = idx >> 11;

    float pos = (float)pos_ids[m];
    float freq = expf(-(float)i * (9.210340371976184f / 64.f));
    float ang = pos * freq;
    float cv = cosf(ang);
    float sv = sinf(ang);

    const float* qs = qkv + (size_t)m * QKVN + h * HD;
    const float* ks = qs + HID;
    float q0 = qs[i], q1 = qs[i + 64];
    float k0 = ks[i], k1 = ks[i + 64];

    size_t o = (size_t)m * HID + h * HD;
    q[o + i]      = q0 * cv - q1 * sv;
    q[o + i + 64] = q1 * cv + q0 * sv;
    k[o + i]      = k0 * cv - k1 * sv;
    k[o + i + 64] = k1 * cv + k0 * sv;
}

// ---------------- causal flash attention (fp32, warp per query row) ----------------
__global__ __launch_bounds__(256)
void attn_kernel(const float* __restrict__ Q, const float* __restrict__ Kg,
                 const float* __restrict__ qkv, float* __restrict__ ctx) {
    const int b = blockIdx.z;
    const int h = blockIdx.y;
    const int warp = threadIdx.x >> 5;
    const int lane = threadIdx.x & 31;
    const int qrow = blockIdx.x * 8 + warp;

    __shared__ float Ks[32][129];
    __shared__ float Vs[32][128];
    __shared__ float Qs[8][128];

    {
        int f = threadIdx.x;
        int r = f >> 5;
        int c4 = (f & 31) << 2;
        *(float4*)&Qs[r][c4] =
            *(const float4*)&Q[((size_t)(b * SEQ + blockIdx.x * 8 + r)) * HID + h * HD + c4];
    }

    float o0 = 0.f, o1 = 0.f, o2 = 0.f, o3 = 0.f;
    float mrun = -INFINITY, lsum = 0.f;
    const float scale = 0.088388347648318447f;
    const int qmax = blockIdx.x * 8 + 7;
    const int ntiles = qmax / 32 + 1;

    for (int t = 0; t < ntiles; t++) {
        __syncthreads();
#pragma unroll
        for (int i = 0; i < 4; i++) {
            int f = threadIdx.x + i * 256;
            int r = f >> 5;
            int c4 = (f & 31) << 2;
            size_t row = (size_t)(b * SEQ + t * 32 + r);
            float4 kv = *(const float4*)&Kg[row * HID + h * HD + c4];
            Ks[r][c4 + 0] = kv.x; Ks[r][c4 + 1] = kv.y;
            Ks[r][c4 + 2] = kv.z; Ks[r][c4 + 3] = kv.w;
            *(float4*)&Vs[r][c4] =
                *(const float4*)&qkv[row * QKVN + 2 * HID + h * HD + c4];
        }
        __syncthreads();

        int kcol = t * 32 + lane;
        float s = 0.f;
        const float* qp = Qs[warp];
#pragma unroll 8
        for (int d = 0; d < 128; d++) s += qp[d] * Ks[lane][d];
        s *= scale;
        if (kcol > qrow) s = -INFINITY;

        float mt = s;
#pragma unroll
        for (int off = 16; off; off >>= 1) mt = fmaxf(mt, __shfl_xor_sync(0xffffffffu, mt, off));
        float mnew = fmaxf(mrun, mt);
        float corr = expf(mrun - mnew);
        float p = expf(s - mnew);
        float psum = p;
#pragma unroll
        for (int off = 16; off; off >>= 1) psum += __shfl_xor_sync(0xffffffffu, psum, off);
        lsum = lsum * corr + psum;
        o0 *= corr; o1 *= corr; o2 *= corr; o3 *= corr;

#pragma unroll
        for (int j = 0; j < 32; j++) {
            float pj = __shfl_sync(0xffffffffu, p, j);
            float4 v = *(const float4*)&Vs[j][lane * 4];
            o0 += pj * v.x; o1 += pj * v.y; o2 += pj * v.z; o3 += pj * v.w;
        }
        mrun = mnew;
    }

    float inv = 1.f / lsum;
    *(float4*)&ctx[((size_t)(b * SEQ + qrow)) * HID + h * HD + lane * 4] =
        make_float4(tf32r(o0 * inv), tf32r(o1 * inv), tf32r(o2 * inv), tf32r(o3 * inv));
}

// ---------------- launch ----------------
extern "C" void kernel_launch(void* const* d_in, const int* in_sizes, int n_in,
                              void* d_out, int out_size) {
    const float* hidden = (const float*)d_in[0];
    const int*   tt     = (const int*)d_in[1];
    const int*   pos    = (const int*)d_in[2];
    const float* wvq    = (const float*)d_in[3];
    const float* wlq    = (const float*)d_in[4];
    const float* wvd    = (const float*)d_in[5];
    const float* wld    = (const float*)d_in[6];
    float* out = (float*)d_out;

    float *qkv_p, *q_p, *k_p, *ctx_p, *hidr_p, *wr_p;
    int *cnt_p, *idx_p;
    cudaGetSymbolAddress((void**)&qkv_p, g_qkv);
    cudaGetSymbolAddress((void**)&q_p, g_q);
    cudaGetSymbolAddress((void**)&k_p, g_k);
    cudaGetSymbolAddress((void**)&ctx_p, g_ctx);
    cudaGetSymbolAddress((void**)&hidr_p, g_hidr);
    cudaGetSymbolAddress((void**)&wr_p, g_wr);
    cudaGetSymbolAddress((void**)&cnt_p, g_cnt);
    cudaGetSymbolAddress((void**)&idx_p, g_idx);

    const int* cnt_vis  = cnt_p;
    const int* cnt_lang = cnt_p + 1;
    const int* idx_vis  = idx_p;
    const int* idx_lang = idx_p + MTOK;

    float* wr_vq = wr_p + WR_VQ;
    float* wr_lq = wr_p + WR_LQ;
    float* wr_vd = wr_p + WR_VD;
    float* wr_ld = wr_p + WR_LD;

    cudaFuncSetAttribute(gemm_tc, cudaFuncAttributeMaxDynamicSharedMemorySize, GEMM_SMEM);

    zero_cnt_kernel<<<1, 32>>>();
    route_kernel<<<MTOK / 256, 256>>>(tt);

    // pre-pass: transpose+round weights, round hidden
    {
        dim3 g1(QKVN / 32, HID / 32);
        trp_round_kernel<<<g1, 256>>>(wvq, wr_vq, QKVN);
        trp_round_kernel<<<g1, 256>>>(wlq, wr_lq, QKVN);
        dim3 g2(HID / 32, HID / 32);
        trp_round_kernel<<<g2, 256>>>(wvd, wr_vd, HID);
        trp_round_kernel<<<g2, 256>>>(wld, wr_ld, HID);
        int n4h = (int)((size_t)MTOK * HID / 4);
        round_tf32_kernel<<<(n4h + 255) / 256, 256>>>((const float4*)hidden, (float4*)hidr_p, n4h);
    }

    // QKV projection per expert over gathered rows
    {
        dim3 grid(MTOK / BM, QKVN / BN);
        gemm_tc<<<grid, 256, GEMM_SMEM>>>(hidr_p, wr_vq, qkv_p, QKVN, idx_vis, cnt_vis);
        gemm_tc<<<grid, 256, GEMM_SMEM>>>(hidr_p, wr_lq, qkv_p, QKVN, idx_lang, cnt_lang);
    }

    // RoPE
    rope_kernel<<<(MTOK * NH * 64) / 256, 256>>>(qkv_p, pos, q_p, k_p);

    // Attention
    {
        dim3 grid(SEQ / 8, NH, BATCH);
        attn_kernel<<<grid, 256>>>(q_p, k_p, qkv_p, ctx_p);
    }

    // Dense projection per expert
    {
        dim3 grid(MTOK / BM, HID / BN);
        gemm_tc<<<grid, 256, GEMM_SMEM>>>(ctx_p, wr_vd, out, HID, idx_vis, cnt_vis);
        gemm_tc<<<grid, 256, GEMM_SMEM>>>(ctx_p, wr_ld, out, HID, idx_lang, cnt_lang);
    }
}

// round 7
// speedup vs baseline: 2.4426x; 2.4426x over previous
#include <cuda_runtime.h>
#include <cuda_bf16.h>
#include <math.h>
#include <stdint.h>

// Problem constants
#define BATCH 2
#define SEQ   2048
#define NH    32
#define HD    128
#define HID   4096           // NH*HD
#define QKVN  12288          // 3*HID
#define MTOK  (BATCH*SEQ)    // 4096 tokens

// GEMM tile config (mma.sync m16n8k8 tf32, ldmatrix fragments)
#define BM 128
#define BN 128
#define BK 32
#define STAGES 3
#define TSTRIDE 36
#define TILE_BYTES (128 * TSTRIDE * 4)
#define STAGE_BYTES (2 * TILE_BYTES)
#define GEMM_SMEM (STAGES * STAGE_BYTES)         // 110592

// Attention smem layout
#define QS_STRIDE 132                            // floats (33 x 16B, odd -> LDSM conflict-free)
#define VS_STRIDE 68                             // floats (17 x 16B, odd)
#define AQS_OFF 0
#define AKS_OFF (128 * QS_STRIDE * 4)            // 67584
#define AVT_OFF (AKS_OFF + 64 * QS_STRIDE * 4)   // 101376
#define APS_OFF (AVT_OFF + 128 * VS_STRIDE * 4)  // 136192
#define ATT_SMEM (APS_OFF + 128 * VS_STRIDE * 4) // 171008

// ---------------- scratch (device globals) -------------
__device__ float g_qkv[(size_t)MTOK * QKVN];
__device__ float g_q[(size_t)MTOK * HID];            // roped*scale, tf32-rounded
__device__ float g_k[(size_t)MTOK * HID];            // roped, tf32-rounded
__device__ float g_vt[(size_t)BATCH * NH * HD * SEQ];// transposed V, tf32-rounded
__device__ float g_ctx[(size_t)MTOK * HID];          // tf32-rounded
__device__ float g_hidr[(size_t)MTOK * HID];         // tf32-rounded hidden
#define WR_VQ 0
#define WR_LQ ((size_t)HID * QKVN)
#define WR_VD (2 * (size_t)HID * QKVN)
#define WR_LD (2 * (size_t)HID * QKVN + (size_t)HID * HID)
__device__ float g_wr[2 * (size_t)HID * QKVN + 2 * (size_t)HID * HID];
__device__ int   g_cnt[2];
__device__ int   g_idx[2][MTOK];

// ---------------- helpers ----------------
__device__ __forceinline__ uint32_t smem_u32(const void* p) {
    uint32_t a;
    asm("{ .reg .u64 t; cvta.to.shared.u64 t, %1; cvt.u32.u64 %0, t; }" : "=r"(a) : "l"(p));
    return a;
}
__device__ __forceinline__ void cp16(uint32_t dst, const void* src) {
    asm volatile("cp.async.cg.shared.global [%0], [%1], 16;" :: "r"(dst), "l"(src));
}
__device__ __forceinline__ void cp_commit() {
    asm volatile("cp.async.commit_group;" ::: "memory");
}
template <int N>
__device__ __forceinline__ void cp_wait() {
    asm volatile("cp.async.wait_group %0;" :: "n"(N) : "memory");
}
__device__ __forceinline__ uint32_t f2tf32(float f) {
    uint32_t r;
    asm("cvt.rna.tf32.f32 %0, %1;" : "=r"(r) : "f"(f));
    return r;
}
__device__ __forceinline__ float tf32r(float f) { return __uint_as_float(f2tf32(f)); }
__device__ __forceinline__ void mma_tf32(float* c, uint32_t a0, uint32_t a1, uint32_t a2, uint32_t a3,
                                         uint32_t b0, uint32_t b1) {
    asm volatile(
        "mma.sync.aligned.m16n8k8.row.col.f32.tf32.tf32.f32 "
        "{%0,%1,%2,%3}, {%4,%5,%6,%7}, {%8,%9}, {%0,%1,%2,%3};"
        : "+f"(c[0]), "+f"(c[1]), "+f"(c[2]), "+f"(c[3])
        : "r"(a0), "r"(a1), "r"(a2), "r"(a3), "r"(b0), "r"(b1));
}
#define LDSM4(r0, r1, r2, r3, addr)                                               \
    asm volatile("ldmatrix.sync.aligned.m8n8.x4.shared.b16 {%0,%1,%2,%3}, [%4];"   \
        : "=r"(r0), "=r"(r1), "=r"(r2), "=r"(r3) : "r"(addr))

// ---------------- pre-passes ----------------
__global__ __launch_bounds__(256)
void round_tf32_kernel(const float4* __restrict__ in, float4* __restrict__ out, int n4) {
    int i = blockIdx.x * blockDim.x + threadIdx.x;
    if (i >= n4) return;
    float4 v = in[i];
    out[i] = make_float4(tf32r(v.x), tf32r(v.y), tf32r(v.z), tf32r(v.w));
}
__global__ __launch_bounds__(256)
void trp_round_kernel(const float* __restrict__ W, float* __restrict__ Wt, int N) {
    __shared__ float t[32][33];
    int bx = blockIdx.x * 32;
    int by = blockIdx.y * 32;
    int x = threadIdx.x & 31;
    int y = threadIdx.x >> 5;
#pragma unroll
    for (int i = 0; i < 32; i += 8)
        t[y + i][x] = W[(size_t)(by + y + i) * N + bx + x];
    __syncthreads();
#pragma unroll
    for (int i = 0; i < 32; i += 8)
        Wt[(size_t)(bx + y + i) * HID + by + x] = tf32r(t[x][y + i]);
}
// V transpose: g_vt[bh][d][s] = tf32r(V[b,s,h,d]) from qkv
__global__ __launch_bounds__(256)
void vtrans_kernel(const float* __restrict__ qkv, float* __restrict__ Vt) {
    __shared__ float t[32][33];
    int bh = blockIdx.z;
    int b = bh >> 5, h = bh & 31;
    int s0 = blockIdx.x * 32;
    int d0 = blockIdx.y * 32;
    int x = threadIdx.x & 31;
    int y = threadIdx.x >> 5;
#pragma unroll
    for (int i = 0; i < 32; i += 8)
        t[y + i][x] = qkv[(size_t)(b * SEQ + s0 + y + i) * QKVN + 2 * HID + h * HD + d0 + x];
    __syncthreads();
#pragma unroll
    for (int i = 0; i < 32; i += 8)
        Vt[((size_t)bh * HD + d0 + y + i) * SEQ + s0 + x] = tf32r(t[x][y + i]);
}

// ---------------- mask / routing ----------------
__global__ void zero_cnt_kernel() {
    if (threadIdx.x < 2) g_cnt[threadIdx.x] = 0;
}
__global__ void route_kernel(const int* __restrict__ tt) {
    int idx = blockIdx.x * blockDim.x + threadIdx.x;
    if (idx >= MTOK) return;
    int s = idx & (SEQ - 1);
    int vis = (s + 1 < SEQ) && (tt[idx] == 1) && (tt[idx + 1] == 1);
    int e = vis ? 0 : 1;
    int pos = atomicAdd(&g_cnt[e], 1);
    g_idx[e][pos] = idx;
}

// ---------------- tensor-core tf32 GEMM (unchanged from round 6) ----------------
__global__ __launch_bounds__(256)
void gemm_tc(const float* __restrict__ A, const float* __restrict__ Wt,
             float* __restrict__ C, int N,
             const int* __restrict__ idx, const int* __restrict__ cnt_ptr) {
    __shared__ int idx_s[BM];
    extern __shared__ char smem[];
    const uint32_t sb = smem_u32(smem);
    const int tid = threadIdx.x;
    const int wid = tid >> 5;
    const int lane = tid & 31;
    const int lm = lane >> 2;
    const int lq = lane & 3;
    const int warp_m = wid & 1;
    const int warp_n = wid >> 1;
    const int m0 = blockIdx.x * BM;
    const int n0 = blockIdx.y * BN;

    const int count = __ldg(cnt_ptr);
    if (m0 >= count) return;

    if (tid < BM) {
        int mp = m0 + tid;
        idx_s[tid] = idx[mp < count ? mp : count - 1];
    }
    __syncthreads();

    int r_ld[4], c_ld[4];
#pragma unroll
    for (int i = 0; i < 4; i++) {
        int t = tid + i * 256;
        r_ld[i] = t >> 3;
        c_ld[i] = t & 7;
    }
    int a_g[4];
#pragma unroll
    for (int i = 0; i < 4; i++) a_g[i] = idx_s[r_ld[i]];

    const float* Bt = Wt + (size_t)n0 * HID;

    auto load_stage = [&](int stage, int chunk) {
        uint32_t as = sb + stage * STAGE_BYTES;
        uint32_t bs = as + TILE_BYTES;
#pragma unroll
        for (int i = 0; i < 4; i++)
            cp16(as + r_ld[i] * (TSTRIDE * 4) + c_ld[i] * 16,
                 A + (size_t)a_g[i] * HID + chunk * BK + c_ld[i] * 4);
#pragma unroll
        for (int i = 0; i < 4; i++)
            cp16(bs + r_ld[i] * (TSTRIDE * 4) + c_ld[i] * 16,
                 Bt + (size_t)r_ld[i] * HID + chunk * BK + c_ld[i] * 4);
    };

    const int a_row = (lane & 7) | (lane & 8);
    const int a_ko  = (lane >> 4) * 4;
    const int b_row = (lane & 7) | ((lane >> 1) & 8);
    const int b_ko  = ((lane >> 3) & 1) * 4;
    const uint32_t a_off = (warp_m * 64 + a_row) * (TSTRIDE * 4) + a_ko * 4;
    const uint32_t b_off = (warp_n * 32 + b_row) * (TSTRIDE * 4) + b_ko * 4;

    float c[4][4][4];
#pragma unroll
    for (int mt = 0; mt < 4; mt++)
#pragma unroll
        for (int nt = 0; nt < 4; nt++)
#pragma unroll
            for (int j = 0; j < 4; j++) c[mt][nt][j] = 0.f;

    const int NC = HID / BK;

    load_stage(0, 0); cp_commit();
    load_stage(1, 1); cp_commit();

    for (int ch = 0; ch < NC; ch++) {
        cp_wait<1>();
        __syncthreads();

        if (ch + 2 < NC) load_stage((ch + 2) % STAGES, ch + 2);
        cp_commit();

        const uint32_t as = sb + (ch % STAGES) * STAGE_BYTES;
        const uint32_t bs = as + TILE_BYTES;
        const uint32_t aL = as + a_off;
        const uint32_t bL = bs + b_off;

#pragma unroll
        for (int kk = 0; kk < BK; kk += 8) {
            uint32_t af[4][4], bf[4][2];
#pragma unroll
            for (int mt = 0; mt < 4; mt++)
                LDSM4(af[mt][0], af[mt][1], af[mt][2], af[mt][3],
                      aL + mt * 16 * (TSTRIDE * 4) + kk * 4);
#pragma unroll
            for (int pr = 0; pr < 2; pr++)
                LDSM4(bf[2 * pr][0], bf[2 * pr][1], bf[2 * pr + 1][0], bf[2 * pr + 1][1],
                      bL + pr * 16 * (TSTRIDE * 4) + kk * 4);
#pragma unroll
            for (int mt = 0; mt < 4; mt++)
#pragma unroll
                for (int nt = 0; nt < 4; nt++)
                    mma_tf32(c[mt][nt], af[mt][0], af[mt][1], af[mt][2], af[mt][3],
                             bf[nt][0], bf[nt][1]);
        }
        __syncthreads();
    }

#pragma unroll
    for (int mt = 0; mt < 4; mt++) {
        int r0 = warp_m * 64 + mt * 16 + lm;
        int r1 = r0 + 8;
        bool on0 = (m0 + r0 < count);
        bool on1 = (m0 + r1 < count);
        float* p0 = C + (size_t)idx_s[r0] * N + n0 + warp_n * 32;
        float* p1 = C + (size_t)idx_s[r1] * N + n0 + warp_n * 32;
#pragma unroll
        for (int nt = 0; nt < 4; nt++) {
            int col = nt * 8 + 2 * lq;
            if (on0) *(float2*)(p0 + col) = make_float2(c[mt][nt][0], c[mt][nt][1]);
            if (on1) *(float2*)(p1 + col) = make_float2(c[mt][nt][2], c[mt][nt][3]);
        }
    }
}

// ---------------- RoPE: q scaled by 1/sqrt(HD), q/k tf32-rounded ----------------
__global__ void rope_kernel(const float* __restrict__ qkv, const int* __restrict__ pos_ids,
                            float* __restrict__ q, float* __restrict__ k) {
    int idx = blockIdx.x * blockDim.x + threadIdx.x;
    if (idx >= MTOK * NH * 64) return;
    int i = idx & 63;
    int h = (idx >> 6) & 31;
    int m = idx >> 11;

    float pos = (float)pos_ids[m];
    float freq = expf(-(float)i * (9.210340371976184f / 64.f));
    float ang = pos * freq;
    float cv = cosf(ang);
    float sv = sinf(ang);
    const float scale = 0.088388347648318447f;  // 1/sqrt(128)

    const float* qs = qkv + (size_t)m * QKVN + h * HD;
    const float* ks = qs + HID;
    float q0 = qs[i], q1 = qs[i + 64];
    float k0 = ks[i], k1 = ks[i + 64];

    size_t o = (size_t)m * HID + h * HD;
    q[o + i]      = tf32r((q0 * cv - q1 * sv) * scale);
    q[o + i + 64] = tf32r((q1 * cv + q0 * sv) * scale);
    k[o + i]      = tf32r(k0 * cv - k1 * sv);
    k[o + i + 64] = tf32r(k1 * cv + k0 * sv);
}

// ---------------- tensor-core flash attention ----------------
// Block: 128 q rows x 1 head; 8 warps x 16 rows. K-tile 64.
__global__ __launch_bounds__(256)
void attn_mma(const float* __restrict__ Q, const float* __restrict__ Kg,
              const float* __restrict__ Vt, float* __restrict__ ctx) {
    extern __shared__ char smem[];
    const uint32_t sb = smem_u32(smem);
    const int tid = threadIdx.x;
    const int warp = tid >> 5;
    const int lane = tid & 31;
    const int lm = lane >> 2;
    const int lq = lane & 3;
    const int b = blockIdx.z;
    const int h = blockIdx.y;
    const int qi = (int)gridDim.x - 1 - (int)blockIdx.x;   // heavy blocks first
    const int qb = qi * 128;

    // load Q tile (128 x 128)
#pragma unroll
    for (int i = 0; i < 16; i++) {
        int g = tid + i * 256;
        int r = g >> 5, c = g & 31;
        cp16(sb + AQS_OFF + r * (QS_STRIDE * 4) + c * 16,
             Q + (size_t)(b * SEQ + qb + r) * HID + h * HD + c * 4);
    }
    cp_commit();

    const int a_row = lane & 15;
    const int a_ko  = (lane >> 4) * 4;
    const int b_row = (lane & 7) | ((lane >> 1) & 8);
    const int b_ko  = ((lane >> 3) & 1) * 4;
    const uint32_t qA = sb + AQS_OFF + (warp * 16 + a_row) * (QS_STRIDE * 4) + a_ko * 4;
    const uint32_t pA = sb + APS_OFF + (warp * 16 + a_row) * (VS_STRIDE * 4) + a_ko * 4;
    const uint32_t kB = sb + AKS_OFF + b_row * (QS_STRIDE * 4) + b_ko * 4;
    const uint32_t vB = sb + AVT_OFF + b_row * (VS_STRIDE * 4) + b_ko * 4;

    float o[16][4];
#pragma unroll
    for (int nt = 0; nt < 16; nt++)
#pragma unroll
        for (int j = 0; j < 4; j++) o[nt][j] = 0.f;
    float mr0 = -1e30f, mr1 = -1e30f, l0 = 0.f, l1 = 0.f;
    const int r0g = qb + warp * 16 + lm;
    const int r1g = r0g + 8;

    const int ntiles = 2 * qi + 2;
    for (int t = 0; t < ntiles; t++) {
        // load K tile (64 x 128) and Vt tile (128 x 64)
#pragma unroll
        for (int i = 0; i < 8; i++) {
            int g = tid + i * 256;
            int r = g >> 5, c = g & 31;
            cp16(sb + AKS_OFF + r * (QS_STRIDE * 4) + c * 16,
                 Kg + (size_t)(b * SEQ + t * 64 + r) * HID + h * HD + c * 4);
        }
#pragma unroll
        for (int i = 0; i < 8; i++) {
            int g = tid + i * 256;
            int r = g >> 4, c = g & 15;
            cp16(sb + AVT_OFF + r * (VS_STRIDE * 4) + c * 16,
                 Vt + ((size_t)(b * NH + h) * HD + r) * SEQ + t * 64 + c * 4);
        }
        cp_commit();
        cp_wait<0>();
        __syncthreads();

        // scores: 16 rows x 64 cols per warp
        float s_[8][4];
#pragma unroll
        for (int nt = 0; nt < 8; nt++)
#pragma unroll
            for (int j = 0; j < 4; j++) s_[nt][j] = 0.f;

#pragma unroll
        for (int ks = 0; ks < 16; ks++) {
            uint32_t a0, a1, a2, a3;
            LDSM4(a0, a1, a2, a3, qA + ks * 32);
#pragma unroll
            for (int pr = 0; pr < 4; pr++) {
                uint32_t b0, b1, b2, b3;
                LDSM4(b0, b1, b2, b3, kB + pr * 16 * (QS_STRIDE * 4) + ks * 32);
                mma_tf32(s_[2 * pr],     a0, a1, a2, a3, b0, b1);
                mma_tf32(s_[2 * pr + 1], a0, a1, a2, a3, b2, b3);
            }
        }

        // causal mask (last two tiles only)
        if (t >= 2 * qi) {
#pragma unroll
            for (int nt = 0; nt < 8; nt++) {
                int cb = t * 64 + nt * 8 + 2 * lq;
                if (cb > r0g)     s_[nt][0] = -1e30f;
                if (cb + 1 > r0g) s_[nt][1] = -1e30f;
                if (cb > r1g)     s_[nt][2] = -1e30f;
                if (cb + 1 > r1g) s_[nt][3] = -1e30f;
            }
        }

        // online softmax
        float tm0 = -1e30f, tm1 = -1e30f;
#pragma unroll
        for (int nt = 0; nt < 8; nt++) {
            tm0 = fmaxf(tm0, fmaxf(s_[nt][0], s_[nt][1]));
            tm1 = fmaxf(tm1, fmaxf(s_[nt][2], s_[nt][3]));
        }
        tm0 = fmaxf(tm0, __shfl_xor_sync(0xffffffffu, tm0, 1));
        tm0 = fmaxf(tm0, __shfl_xor_sync(0xffffffffu, tm0, 2));
        tm1 = fmaxf(tm1, __shfl_xor_sync(0xffffffffu, tm1, 1));
        tm1 = fmaxf(tm1, __shfl_xor_sync(0xffffffffu, tm1, 2));
        float mn0 = fmaxf(mr0, tm0), mn1 = fmaxf(mr1, tm1);
        float c0 = __expf(mr0 - mn0), c1 = __expf(mr1 - mn1);
        float ps0 = 0.f, ps1 = 0.f;
#pragma unroll
        for (int nt = 0; nt < 8; nt++) {
            s_[nt][0] = __expf(s_[nt][0] - mn0);
            s_[nt][1] = __expf(s_[nt][1] - mn0);
            s_[nt][2] = __expf(s_[nt][2] - mn1);
            s_[nt][3] = __expf(s_[nt][3] - mn1);
            ps0 += s_[nt][0] + s_[nt][1];
            ps1 += s_[nt][2] + s_[nt][3];
        }
        l0 = l0 * c0 + ps0;
        l1 = l1 * c1 + ps1;
#pragma unroll
        for (int nt = 0; nt < 16; nt++) {
            o[nt][0] *= c0; o[nt][1] *= c0;
            o[nt][2] *= c1; o[nt][3] *= c1;
        }
        mr0 = mn0; mr1 = mn1;

        // P -> smem (warp-private rows)
#pragma unroll
        for (int nt = 0; nt < 8; nt++) {
            *(float2*)(smem + APS_OFF + (warp * 16 + lm) * (VS_STRIDE * 4) + (nt * 8 + 2 * lq) * 4)
                = make_float2(tf32r(s_[nt][0]), tf32r(s_[nt][1]));
            *(float2*)(smem + APS_OFF + (warp * 16 + lm + 8) * (VS_STRIDE * 4) + (nt * 8 + 2 * lq) * 4)
                = make_float2(tf32r(s_[nt][2]), tf32r(s_[nt][3]));
        }
        __syncwarp();

        // PV: O[16 x 128] += P[16 x 64] * V[64 x 128]
#pragma unroll
        for (int ks = 0; ks < 8; ks++) {
            uint32_t a0, a1, a2, a3;
            LDSM4(a0, a1, a2, a3, pA + ks * 32);
#pragma unroll
            for (int pr = 0; pr < 8; pr++) {
                uint32_t b0, b1, b2, b3;
                LDSM4(b0, b1, b2, b3, vB + pr * 16 * (VS_STRIDE * 4) + ks * 32);
                mma_tf32(o[2 * pr],     a0, a1, a2, a3, b0, b1);
                mma_tf32(o[2 * pr + 1], a0, a1, a2, a3, b2, b3);
            }
        }
        __syncthreads();
    }

    l0 += __shfl_xor_sync(0xffffffffu, l0, 1);
    l0 += __shfl_xor_sync(0xffffffffu, l0, 2);
    l1 += __shfl_xor_sync(0xffffffffu, l1, 1);
    l1 += __shfl_xor_sync(0xffffffffu, l1, 2);
    float i0 = 1.f / l0, i1 = 1.f / l1;

#pragma unroll
    for (int nt = 0; nt < 16; nt++) {
        int col = nt * 8 + 2 * lq;
        *(float2*)&ctx[(size_t)(b * SEQ + r0g) * HID + h * HD + col] =
            make_float2(tf32r(o[nt][0] * i0), tf32r(o[nt][1] * i0));
        *(float2*)&ctx[(size_t)(b * SEQ + r1g) * HID + h * HD + col] =
            make_float2(tf32r(o[nt][2] * i1), tf32r(o[nt][3] * i1));
    }
}

// ---------------- launch ----------------
extern "C" void kernel_launch(void* const* d_in, const int* in_sizes, int n_in,
                              void* d_out, int out_size) {
    const float* hidden = (const float*)d_in[0];
    const int*   tt     = (const int*)d_in[1];
    const int*   pos    = (const int*)d_in[2];
    const float* wvq    = (const float*)d_in[3];
    const float* wlq    = (const float*)d_in[4];
    const float* wvd    = (const float*)d_in[5];
    const float* wld    = (const float*)d_in[6];
    float* out = (float*)d_out;

    float *qkv_p, *q_p, *k_p, *vt_p, *ctx_p, *hidr_p, *wr_p;
    int *cnt_p, *idx_p;
    cudaGetSymbolAddress((void**)&qkv_p, g_qkv);
    cudaGetSymbolAddress((void**)&q_p, g_q);
    cudaGetSymbolAddress((void**)&k_p, g_k);
    cudaGetSymbolAddress((void**)&vt_p, g_vt);
    cudaGetSymbolAddress((void**)&ctx_p, g_ctx);
    cudaGetSymbolAddress((void**)&hidr_p, g_hidr);
    cudaGetSymbolAddress((void**)&wr_p, g_wr);
    cudaGetSymbolAddress((void**)&cnt_p, g_cnt);
    cudaGetSymbolAddress((void**)&idx_p, g_idx);

    const int* cnt_vis  = cnt_p;
    const int* cnt_lang = cnt_p + 1;
    const int* idx_vis  = idx_p;
    const int* idx_lang = idx_p + MTOK;

    float* wr_vq = wr_p + WR_VQ;
    float* wr_lq = wr_p + WR_LQ;
    float* wr_vd = wr_p + WR_VD;
    float* wr_ld = wr_p + WR_LD;

    cudaFuncSetAttribute(gemm_tc, cudaFuncAttributeMaxDynamicSharedMemorySize, GEMM_SMEM);
    cudaFuncSetAttribute(attn_mma, cudaFuncAttributeMaxDynamicSharedMemorySize, ATT_SMEM);

    zero_cnt_kernel<<<1, 32>>>();
    route_kernel<<<MTOK / 256, 256>>>(tt);

    // pre-pass: transpose+round weights, round hidden
    {
        dim3 g1(QKVN / 32, HID / 32);
        trp_round_kernel<<<g1, 256>>>(wvq, wr_vq, QKVN);
        trp_round_kernel<<<g1, 256>>>(wlq, wr_lq, QKVN);
        dim3 g2(HID / 32, HID / 32);
        trp_round_kernel<<<g2, 256>>>(wvd, wr_vd, HID);
        trp_round_kernel<<<g2, 256>>>(wld, wr_ld, HID);
        int n4h = (int)((size_t)MTOK * HID / 4);
        round_tf32_kernel<<<(n4h + 255) / 256, 256>>>((const float4*)hidden, (float4*)hidr_p, n4h);
    }

    // QKV projection per expert over gathered rows
    {
        dim3 grid(MTOK / BM, QKVN / BN);
        gemm_tc<<<grid, 256, GEMM_SMEM>>>(hidr_p, wr_vq, qkv_p, QKVN, idx_vis, cnt_vis);
        gemm_tc<<<grid, 256, GEMM_SMEM>>>(hidr_p, wr_lq, qkv_p, QKVN, idx_lang, cnt_lang);
    }

    // RoPE (scaled q, tf32-rounded) + V transpose
    rope_kernel<<<(MTOK * NH * 64) / 256, 256>>>(qkv_p, pos, q_p, k_p);
    {
        dim3 gv(SEQ / 32, HD / 32, BATCH * NH);
        vtrans_kernel<<<gv, 256>>>(qkv_p, vt_p);
    }

    // Tensor-core flash attention
    {
        dim3 grid(SEQ / 128, NH, BATCH);
        attn_mma<<<grid, 256, ATT_SMEM>>>(q_p, k_p, vt_p, ctx_p);
    }

    // Dense projection per expert
    {
        dim3 grid(MTOK / BM, HID / BN);
        gemm_tc<<<grid, 256, GEMM_SMEM>>>(ctx_p, wr_vd, out, HID, idx_vis, cnt_vis);
        gemm_tc<<<grid, 256, GEMM_SMEM>>>(ctx_p, wr_ld, out, HID, idx_lang, cnt_lang);
    }
}